// round 6
// baseline (speedup 1.0000x reference)
#include <cuda_runtime.h>
#include <cstdint>

namespace {
constexpr int NS    = 512;
constexpr int MPTS  = 8192;
constexpr int HW4   = 4096;     // float4 words per 128x128 plane
constexpr int BLOCK = 256;
}

__device__ __forceinline__ float frcp(float x)  { float r; asm("rcp.approx.f32 %0,%1;"  : "=f"(r) : "f"(x)); return r; }
__device__ __forceinline__ float fsqrt(float x) { float r; asm("sqrt.approx.f32 %0,%1;" : "=f"(r) : "f"(x)); return r; }

__global__ void __launch_bounds__(BLOCK, 6) score_kernel(
    const int*   __restrict__ obj_id,
    const float* __restrict__ camK,
    const float* __restrict__ Rg_all,
    const float* __restrict__ tg_all,
    const float* __restrict__ Rp_all,
    const float* __restrict__ tp_all,
    const float* __restrict__ coord,
    const void*  __restrict__ mask,
    const float* __restrict__ mesh,
    const float* __restrict__ diam,
    float*       __restrict__ out)     // [5*NS]: re|te|ad|pj|pv
{
    const int tid  = threadIdx.x;
    const int lane = tid & 31;
    const int wid  = tid >> 5;
    const int b    = blockIdx.x;
    const bool is_pv = (b < NS);
    const int n    = is_pv ? b : b - NS;

    __shared__ float sr0[8], sr1[8];
    __shared__ int   smode;

    // ---- mask dtype detection (warp 0, first 512B; L2-broadcast across blocks) ----
    if (wid == 0) {
        const unsigned* mw = (const unsigned*)mask;
        unsigned f = 0, o = 0;
#pragma unroll
        for (int k = 0; k < 4; k++) {
            unsigned w = __ldg(mw + lane + 32 * k);
            if (w == 0x3F800000u) f = 1;
            else if (w > 1u) o = 1;
        }
        f = __any_sync(0xFFFFFFFFu, f);
        o = __any_sync(0xFFFFFFFFu, o);
        if (lane == 0) smode = f ? 0 : (o ? 2 : 1);   // 0=f32 1=i32 2=packed u8
    }

    // ---- per-sample constants (broadcast) ----
    float Rp[9], Rg[9];
#pragma unroll
    for (int i = 0; i < 9; i++) {
        Rp[i] = __ldg(Rp_all + n * 9 + i);
        Rg[i] = __ldg(Rg_all + n * 9 + i);
    }
    const float tp0 = __ldg(tp_all + n*3+0), tp1 = __ldg(tp_all + n*3+1), tp2 = __ldg(tp_all + n*3+2);
    const float tg0 = __ldg(tg_all + n*3+0), tg1 = __ldg(tg_all + n*3+1), tg2 = __ldg(tg_all + n*3+2);
    const float fx  = __ldg(camK + n*9 + 0), fy = __ldg(camK + n*9 + 4);

    __syncthreads();
    const int mode = smode;

    float r0 = 0.f, r1 = 0.f;

    if (is_pv) {
        // ================= PV: 16384 ROI pixels (4096 float4) =================
        const float4* c4 = (const float4*)coord + (size_t)n * 3 * HW4;
        const size_t mbase = (size_t)n * HW4;
#pragma unroll 2
        for (int it = 0; it < HW4 / BLOCK; ++it) {
            const int f = it * BLOCK + tid;
            float4 X = c4[f], Y = c4[f + HW4], Z = c4[f + 2 * HW4];
            float mv[4];
            if (mode == 0) {
                float4 M = ((const float4*)mask)[mbase + f];
                mv[0] = M.x; mv[1] = M.y; mv[2] = M.z; mv[3] = M.w;
            } else if (mode == 1) {
                int4 M = ((const int4*)mask)[mbase + f];
                mv[0] = (float)M.x; mv[1] = (float)M.y; mv[2] = (float)M.z; mv[3] = (float)M.w;
            } else {
                unsigned w = ((const unsigned*)mask)[mbase + f];
                mv[0] = (float)(w & 255u);         mv[1] = (float)((w >> 8) & 255u);
                mv[2] = (float)((w >> 16) & 255u); mv[3] = (float)(w >> 24);
            }
            const float xs[4] = {X.x, X.y, X.z, X.w};
            const float ys[4] = {Y.x, Y.y, Y.z, Y.w};
            const float zs[4] = {Z.x, Z.y, Z.z, Z.w};
#pragma unroll
            for (int k = 0; k < 4; k++) {
                const float v0 = xs[k], v1 = ys[k], v2 = zs[k];
                float p0 = fmaf(Rp[0], v0, fmaf(Rp[1], v1, fmaf(Rp[2], v2, tp0)));
                float p1 = fmaf(Rp[3], v0, fmaf(Rp[4], v1, fmaf(Rp[5], v2, tp1)));
                float p2 = fmaf(Rp[6], v0, fmaf(Rp[7], v1, fmaf(Rp[8], v2, tp2)));
                float g0 = fmaf(Rg[0], v0, fmaf(Rg[1], v1, fmaf(Rg[2], v2, tg0)));
                float g1 = fmaf(Rg[3], v0, fmaf(Rg[4], v1, fmaf(Rg[5], v2, tg1)));
                float g2 = fmaf(Rg[6], v0, fmaf(Rg[7], v1, fmaf(Rg[8], v2, tg2)));
                // p0/p2 - g0/g2 = (p0*g2 - g0*p2)/(p2*g2): one MUFU rcp (z>0 always)
                float t0 = fmaf(p0, g2, -(g0 * p2));
                float t1 = fmaf(p1, g2, -(g1 * p2));
                float r  = frcp(p2 * g2);
                float du = fx * (t0 * r);
                float dv = fy * (t1 * r);
                float d  = fsqrt(fmaf(du, du, dv * dv));
                r0 = fmaf(d, mv[k], r0);
                r1 += mv[k];
            }
        }
    } else {
        // ================= MESH: 8192 points (4 pts per 3 float4) =================
        const int obj = __ldg(obj_id + n);
        float dR[9];
#pragma unroll
        for (int i = 0; i < 9; i++) dR[i] = Rp[i] - Rg[i];
        const float dt0 = tp0 - tg0, dt1 = tp1 - tg1, dt2 = tp2 - tg2;

        const float4* m4 = (const float4*)mesh + (size_t)obj * (MPTS * 3 / 4);
#pragma unroll 2
        for (int g = 0; g < MPTS / (BLOCK * 4); ++g) {
            const int base3 = (g * BLOCK + tid) * 3;
            float4 A = __ldg(m4 + base3);
            float4 B = __ldg(m4 + base3 + 1);
            float4 C = __ldg(m4 + base3 + 2);
            const float px[4] = {A.x, A.w, B.z, C.y};
            const float py[4] = {A.y, B.x, B.w, C.z};
            const float pz[4] = {A.z, B.y, C.x, C.w};
#pragma unroll
            for (int k = 0; k < 4; k++) {
                const float v0 = px[k], v1 = py[k], v2 = pz[k];
                float e0 = fmaf(dR[0], v0, fmaf(dR[1], v1, fmaf(dR[2], v2, dt0)));
                float e1 = fmaf(dR[3], v0, fmaf(dR[4], v1, fmaf(dR[5], v2, dt1)));
                float e2 = fmaf(dR[6], v0, fmaf(dR[7], v1, fmaf(dR[8], v2, dt2)));
                float g0 = fmaf(Rg[0], v0, fmaf(Rg[1], v1, fmaf(Rg[2], v2, tg0)));
                float g1 = fmaf(Rg[3], v0, fmaf(Rg[4], v1, fmaf(Rg[5], v2, tg1)));
                float g2 = fmaf(Rg[6], v0, fmaf(Rg[7], v1, fmaf(Rg[8], v2, tg2)));
                r0 += fsqrt(fmaf(e0, e0, fmaf(e1, e1, e2 * e2)));
                // p = g + e; p0/p2 - g0/g2 = (e0*g2 - g0*e2)/(p2*g2)
                float t0 = fmaf(e0, g2, -(g0 * e2));
                float t1 = fmaf(e1, g2, -(g1 * e2));
                float p2 = g2 + e2;
                float r  = frcp(p2 * g2);
                float du = fx * (t0 * r);
                float dv = fy * (t1 * r);
                r1 += fsqrt(fmaf(du, du, dv * dv));
            }
        }
    }

    // ---- block reduction (8 warps) ----
#pragma unroll
    for (int s = 16; s; s >>= 1) {
        r0 += __shfl_down_sync(0xFFFFFFFFu, r0, s);
        r1 += __shfl_down_sync(0xFFFFFFFFu, r1, s);
    }
    if (lane == 0) { sr0[wid] = r0; sr1[wid] = r1; }
    __syncthreads();

    if (tid == 0) {
        float s0 = 0.f, s1 = 0.f;
#pragma unroll
        for (int k = 0; k < 8; k++) { s0 += sr0[k]; s1 += sr1[k]; }
        if (is_pv) {
            out[4 * NS + n] = s0 / fmaxf(s1, 1.0f);
        } else {
            const int obj = __ldg(obj_id + n);
            out[2 * NS + n] = s0 * (1.0f / MPTS) / __ldg(diam + obj);
            out[3 * NS + n] = s1 * (1.0f / MPTS);
            float tr = 0.f;
#pragma unroll
            for (int i = 0; i < 9; i++) tr = fmaf(Rp[i], Rg[i], tr);
            tr = fminf(fmaxf(tr, -1.0f), 3.0f);
            out[n] = acosf((tr - 1.0f) * 0.5f) * 57.29577951308232f;
            const float d0 = tp0 - tg0, d1 = tp1 - tg1, d2 = tp2 - tg2;
            out[NS + n] = sqrtf(fmaf(d0, d0, fmaf(d1, d1, d2 * d2))) * 100.0f;
        }
    }
}

extern "C" void kernel_launch(void* const* d_in, const int* in_sizes, int n_in,
                              void* d_out, int out_size) {
    (void)in_sizes; (void)n_in; (void)out_size;
    const int*   obj_id = (const int*)  d_in[0];
    const float* camK   = (const float*)d_in[1];
    const float* gtR    = (const float*)d_in[2];
    const float* gtT    = (const float*)d_in[3];
    const float* prR    = (const float*)d_in[4];
    const float* prT    = (const float*)d_in[5];
    const float* coord  = (const float*)d_in[6];
    const void*  mask   =               d_in[7];
    const float* mesh   = (const float*)d_in[8];
    const float* diam   = (const float*)d_in[9];
    float* out = (float*)d_out;

    score_kernel<<<2 * NS, BLOCK>>>(obj_id, camK, gtR, gtT, prR, prT,
                                    coord, mask, mesh, diam, out);
}

// round 7
// speedup vs baseline: 1.4268x; 1.4268x over previous
#include <cuda_runtime.h>
#include <cstdint>

namespace {
constexpr int NS    = 512;
constexpr int MPTS  = 8192;
constexpr int HW    = 16384;
constexpr int HW4   = 4096;
constexpr int BLOCK = 256;
}

__device__ __forceinline__ float frcp(float x)  { float r; asm("rcp.approx.f32 %0,%1;"  : "=f"(r) : "f"(x)); return r; }
__device__ __forceinline__ float fsqrt(float x) { float r; asm("sqrt.approx.f32 %0,%1;" : "=f"(r) : "f"(x)); return r; }

__global__ void __launch_bounds__(BLOCK) score_kernel(
    const int*   __restrict__ obj_id,
    const float* __restrict__ camK,
    const float* __restrict__ Rg_all,
    const float* __restrict__ tg_all,
    const float* __restrict__ Rp_all,
    const float* __restrict__ tp_all,
    const float* __restrict__ coord,    // [N,3,H,W]
    const void*  __restrict__ mask,     // [N,1,H,W]
    const float* __restrict__ mesh,     // [NOBJ,M,3]
    const float* __restrict__ diam,
    float*       __restrict__ out)      // [5*N]: re|te|ad|pj|pv
{
    const int tid  = threadIdx.x;
    const int lane = tid & 31;
    const int b    = blockIdx.x;
    const bool is_pv = (b < NS);
    const int n    = is_pv ? b : b - NS;

    __shared__ float s1[256];
    __shared__ float s2[256];
    __shared__ int   smode;

    // ---- mask dtype detection (warp 0 reads first 512B; L2-broadcast) ----
    if (tid < 32) {
        const unsigned* mw = (const unsigned*)mask;
        unsigned f = 0, o = 0;
#pragma unroll
        for (int k = 0; k < 4; k++) {
            unsigned w = __ldg(mw + lane + 32 * k);
            if (w == 0x3F800000u) f = 1;
            else if (w > 1u) o = 1;
        }
        f = __any_sync(0xFFFFFFFFu, f);
        o = __any_sync(0xFFFFFFFFu, o);
        if (lane == 0) smode = f ? 0 : (o ? 2 : 1);   // 0=f32 1=i32 2=packed u8
    }

    // ---- per-sample constants (broadcast loads, cached) ----
    float Rp[9], Rg[9], tp[3], tg[3];
#pragma unroll
    for (int i = 0; i < 9; i++) { Rp[i] = Rp_all[n * 9 + i]; Rg[i] = Rg_all[n * 9 + i]; }
#pragma unroll
    for (int i = 0; i < 3; i++) { tp[i] = tp_all[n * 3 + i]; tg[i] = tg_all[n * 3 + i]; }
    const float fx = camK[n * 9 + 0];
    const float fy = camK[n * 9 + 4];

    __syncthreads();
    const int mode = smode;

    if (is_pv) {
        // ---- PROJ-visible over ROI pixels ----
        const float4* x4 = (const float4*)(coord + (size_t)n * 3 * HW);
        const float4* y4 = x4 + HW4;
        const float4* z4 = y4 + HW4;
        float sum = 0.f, cnt = 0.f;

#pragma unroll 4
        for (int i = tid; i < HW4; i += BLOCK) {
            float4 X = x4[i], Y = y4[i], Z = z4[i];
            float mv[4];
            if (mode == 0) {
                float4 mm = ((const float4*)mask)[(size_t)n * HW4 + i];
                mv[0] = mm.x; mv[1] = mm.y; mv[2] = mm.z; mv[3] = mm.w;
            } else if (mode == 1) {
                int4 mm = ((const int4*)mask)[(size_t)n * HW4 + i];
                mv[0] = (float)mm.x; mv[1] = (float)mm.y;
                mv[2] = (float)mm.z; mv[3] = (float)mm.w;
            } else {
                unsigned w = ((const unsigned*)mask)[(size_t)n * HW4 + i];
                mv[0] = (float)(w & 0xFFu);
                mv[1] = (float)((w >> 8) & 0xFFu);
                mv[2] = (float)((w >> 16) & 0xFFu);
                mv[3] = (float)(w >> 24);
            }
            const float xs[4] = {X.x, X.y, X.z, X.w};
            const float ys[4] = {Y.x, Y.y, Y.z, Y.w};
            const float zs[4] = {Z.x, Z.y, Z.z, Z.w};
#pragma unroll
            for (int k = 0; k < 4; k++) {
                const float v0 = xs[k], v1 = ys[k], v2 = zs[k];
                float p0 = fmaf(Rp[0], v0, fmaf(Rp[1], v1, fmaf(Rp[2], v2, tp[0])));
                float p1 = fmaf(Rp[3], v0, fmaf(Rp[4], v1, fmaf(Rp[5], v2, tp[1])));
                float p2 = fmaf(Rp[6], v0, fmaf(Rp[7], v1, fmaf(Rp[8], v2, tp[2])));
                float g0 = fmaf(Rg[0], v0, fmaf(Rg[1], v1, fmaf(Rg[2], v2, tg[0])));
                float g1 = fmaf(Rg[3], v0, fmaf(Rg[4], v1, fmaf(Rg[5], v2, tg[1])));
                float g2 = fmaf(Rg[6], v0, fmaf(Rg[7], v1, fmaf(Rg[8], v2, tg[2])));
                // p0/p2 - g0/g2 = (p0*g2 - g0*p2)/(p2*g2): one MUFU rcp (z > 0)
                float t0 = fmaf(p0, g2, -(g0 * p2));
                float t1 = fmaf(p1, g2, -(g1 * p2));
                float r  = frcp(p2 * g2);
                float du = fx * (t0 * r);
                float dv = fy * (t1 * r);
                float d  = fsqrt(fmaf(du, du, dv * dv));
                sum = fmaf(d, mv[k], sum);
                cnt += mv[k];
            }
        }
        s1[tid] = sum; s2[tid] = cnt;
        __syncthreads();
        for (int s = 128; s > 0; s >>= 1) {
            if (tid < s) { s1[tid] += s1[tid + s]; s2[tid] += s2[tid + s]; }
            __syncthreads();
        }
        if (tid == 0) out[4 * NS + n] = s1[0] / fmaxf(s2[0], 1.0f);
    } else {
        // ---- ADD + PROJ over mesh points (+ RE/TE) ----
        const int obj = obj_id[n];
        const float* mp = mesh + (size_t)obj * MPTS * 3;
        float dR[9];
#pragma unroll
        for (int i = 0; i < 9; i++) dR[i] = Rp[i] - Rg[i];
        const float dt0 = tp[0] - tg[0], dt1 = tp[1] - tg[1], dt2 = tp[2] - tg[2];
        float adsum = 0.f, pjsum = 0.f;

#pragma unroll 4
        for (int m = tid; m < MPTS; m += BLOCK) {
            const float v0 = __ldg(mp + m * 3 + 0);
            const float v1 = __ldg(mp + m * 3 + 1);
            const float v2 = __ldg(mp + m * 3 + 2);
            float e0 = fmaf(dR[0], v0, fmaf(dR[1], v1, fmaf(dR[2], v2, dt0)));
            float e1 = fmaf(dR[3], v0, fmaf(dR[4], v1, fmaf(dR[5], v2, dt1)));
            float e2 = fmaf(dR[6], v0, fmaf(dR[7], v1, fmaf(dR[8], v2, dt2)));
            float g0 = fmaf(Rg[0], v0, fmaf(Rg[1], v1, fmaf(Rg[2], v2, tg[0])));
            float g1 = fmaf(Rg[3], v0, fmaf(Rg[4], v1, fmaf(Rg[5], v2, tg[1])));
            float g2 = fmaf(Rg[6], v0, fmaf(Rg[7], v1, fmaf(Rg[8], v2, tg[2])));
            adsum += fsqrt(fmaf(e0, e0, fmaf(e1, e1, e2 * e2)));
            // p = g + e; p0/p2 - g0/g2 = (e0*g2 - g0*e2)/(p2*g2)
            float t0 = fmaf(e0, g2, -(g0 * e2));
            float t1 = fmaf(e1, g2, -(g1 * e2));
            float p2 = g2 + e2;
            float r  = frcp(p2 * g2);
            float du = fx * (t0 * r);
            float dv = fy * (t1 * r);
            pjsum += fsqrt(fmaf(du, du, dv * dv));
        }
        s1[tid] = adsum; s2[tid] = pjsum;
        __syncthreads();
        for (int s = 128; s > 0; s >>= 1) {
            if (tid < s) { s1[tid] += s1[tid + s]; s2[tid] += s2[tid + s]; }
            __syncthreads();
        }
        if (tid == 0) {
            const float invM = 1.0f / (float)MPTS;
            out[2 * NS + n] = (s1[0] * invM) / __ldg(diam + obj);
            out[3 * NS + n] = s2[0] * invM;
            float tr = 0.f;
#pragma unroll
            for (int i = 0; i < 9; i++) tr = fmaf(Rp[i], Rg[i], tr);
            tr = fminf(fmaxf(tr, -1.0f), 3.0f);
            out[n] = acosf((tr - 1.0f) * 0.5f) * 57.29577951308232f;
            out[NS + n] = sqrtf(fmaf(dt0, dt0, fmaf(dt1, dt1, dt2 * dt2))) * 100.0f;
        }
    }
}

extern "C" void kernel_launch(void* const* d_in, const int* in_sizes, int n_in,
                              void* d_out, int out_size) {
    (void)in_sizes; (void)n_in; (void)out_size;
    const int*   obj_id = (const int*)  d_in[0];
    const float* camK   = (const float*)d_in[1];
    const float* gtR    = (const float*)d_in[2];
    const float* gtT    = (const float*)d_in[3];
    const float* prR    = (const float*)d_in[4];
    const float* prT    = (const float*)d_in[5];
    const float* coord  = (const float*)d_in[6];
    const void*  mask   =               d_in[7];
    const float* mesh   = (const float*)d_in[8];
    const float* diam   = (const float*)d_in[9];
    float* out = (float*)d_out;

    score_kernel<<<2 * NS, BLOCK>>>(obj_id, camK, gtR, gtT, prR, prT,
                                    coord, mask, mesh, diam, out);
}

// round 11
// speedup vs baseline: 1.6027x; 1.1233x over previous
#include <cuda_runtime.h>
#include <cstdint>

namespace {
constexpr int NS    = 512;
constexpr int MPTS  = 8192;
constexpr int HW    = 16384;
constexpr int HW4   = 4096;
constexpr int BLOCK = 256;
}

__device__ __forceinline__ float frcp(float x)  { float r; asm("rcp.approx.f32 %0,%1;"  : "=f"(r) : "f"(x)); return r; }
__device__ __forceinline__ float fsqrt(float x) { float r; asm("sqrt.approx.f32 %0,%1;" : "=f"(r) : "f"(x)); return r; }

__global__ void __launch_bounds__(BLOCK) score_kernel(
    const int*   __restrict__ obj_id,
    const float* __restrict__ camK,
    const float* __restrict__ Rg_all,
    const float* __restrict__ tg_all,
    const float* __restrict__ Rp_all,
    const float* __restrict__ tp_all,
    const float* __restrict__ coord,    // [N,3,H,W]
    const void*  __restrict__ mask,     // [N,1,H,W]
    const float* __restrict__ mesh,     // [NOBJ,M,3]
    const float* __restrict__ diam,
    float*       __restrict__ out)      // [5*N]: re|te|ad|pj|pv
{
    const int tid  = threadIdx.x;
    const int lane = tid & 31;
    const int b    = blockIdx.x;
    const bool is_pv = (b < NS);
    const int n    = is_pv ? b : b - NS;

    __shared__ float s1[256];
    __shared__ float s2[256];
    __shared__ int   smode;

    // ---- mask dtype detection (warp 0 reads first 512B; L2-broadcast) ----
    if (tid < 32) {
        const unsigned* mw = (const unsigned*)mask;
        unsigned f = 0, o = 0;
#pragma unroll
        for (int k = 0; k < 4; k++) {
            unsigned w = __ldg(mw + lane + 32 * k);
            if (w == 0x3F800000u) f = 1;
            else if (w > 1u) o = 1;
        }
        f = __any_sync(0xFFFFFFFFu, f);
        o = __any_sync(0xFFFFFFFFu, o);
        if (lane == 0) smode = f ? 0 : (o ? 2 : 1);   // 0=f32 1=i32 2=packed u8
    }

    // ---- per-sample constants (broadcast loads, cached) ----
    float Rp[9], Rg[9], tp[3], tg[3];
#pragma unroll
    for (int i = 0; i < 9; i++) { Rp[i] = Rp_all[n * 9 + i]; Rg[i] = Rg_all[n * 9 + i]; }
#pragma unroll
    for (int i = 0; i < 3; i++) { tp[i] = tp_all[n * 3 + i]; tg[i] = tg_all[n * 3 + i]; }
    const float fx = camK[n * 9 + 0];
    const float fy = camK[n * 9 + 4];

    __syncthreads();
    const int mode = smode;

    if (is_pv) {
        // ---- PROJ-visible over ROI pixels ----
        const float4* x4 = (const float4*)(coord + (size_t)n * 3 * HW);
        const float4* y4 = x4 + HW4;
        const float4* z4 = y4 + HW4;
        float sum = 0.f, cnt = 0.f;

        for (int i = tid; i < HW4; i += BLOCK) {
            float4 X = x4[i], Y = y4[i], Z = z4[i];
            float mv[4];
            if (mode == 0) {
                float4 mm = ((const float4*)mask)[(size_t)n * HW4 + i];
                mv[0] = mm.x; mv[1] = mm.y; mv[2] = mm.z; mv[3] = mm.w;
            } else if (mode == 1) {
                int4 mm = ((const int4*)mask)[(size_t)n * HW4 + i];
                mv[0] = (float)mm.x; mv[1] = (float)mm.y;
                mv[2] = (float)mm.z; mv[3] = (float)mm.w;
            } else {
                unsigned w = ((const unsigned*)mask)[(size_t)n * HW4 + i];
                mv[0] = (float)(w & 0xFFu);
                mv[1] = (float)((w >> 8) & 0xFFu);
                mv[2] = (float)((w >> 16) & 0xFFu);
                mv[3] = (float)(w >> 24);
            }
            const float xs[4] = {X.x, X.y, X.z, X.w};
            const float ys[4] = {Y.x, Y.y, Y.z, Y.w};
            const float zs[4] = {Z.x, Z.y, Z.z, Z.w};
#pragma unroll
            for (int k = 0; k < 4; k++) {
                const float v0 = xs[k], v1 = ys[k], v2 = zs[k];
                float p0 = fmaf(Rp[0], v0, fmaf(Rp[1], v1, fmaf(Rp[2], v2, tp[0])));
                float p1 = fmaf(Rp[3], v0, fmaf(Rp[4], v1, fmaf(Rp[5], v2, tp[1])));
                float p2 = fmaf(Rp[6], v0, fmaf(Rp[7], v1, fmaf(Rp[8], v2, tp[2])));
                float g0 = fmaf(Rg[0], v0, fmaf(Rg[1], v1, fmaf(Rg[2], v2, tg[0])));
                float g1 = fmaf(Rg[3], v0, fmaf(Rg[4], v1, fmaf(Rg[5], v2, tg[1])));
                float g2 = fmaf(Rg[6], v0, fmaf(Rg[7], v1, fmaf(Rg[8], v2, tg[2])));
                // p0/p2 - g0/g2 = (p0*g2 - g0*p2)/(p2*g2): one MUFU rcp (z > 0)
                float t0 = fmaf(p0, g2, -(g0 * p2));
                float t1 = fmaf(p1, g2, -(g1 * p2));
                float r  = frcp(p2 * g2);
                float du = fx * (t0 * r);
                float dv = fy * (t1 * r);
                float d  = fsqrt(fmaf(du, du, dv * dv));
                sum = fmaf(d, mv[k], sum);
                cnt += mv[k];
            }
        }
        s1[tid] = sum; s2[tid] = cnt;
        __syncthreads();
        for (int s = 128; s > 0; s >>= 1) {
            if (tid < s) { s1[tid] += s1[tid + s]; s2[tid] += s2[tid + s]; }
            __syncthreads();
        }
        if (tid == 0) out[4 * NS + n] = s1[0] / fmaxf(s2[0], 1.0f);
    } else {
        // ---- ADD + PROJ over mesh points (+ RE/TE) ----
        const int obj = obj_id[n];
        const float* mp = mesh + (size_t)obj * MPTS * 3;
        float dR[9];
#pragma unroll
        for (int i = 0; i < 9; i++) dR[i] = Rp[i] - Rg[i];
        const float dt0 = tp[0] - tg[0], dt1 = tp[1] - tg[1], dt2 = tp[2] - tg[2];
        float adsum = 0.f, pjsum = 0.f;

        for (int m = tid; m < MPTS; m += BLOCK) {
            const float v0 = __ldg(mp + m * 3 + 0);
            const float v1 = __ldg(mp + m * 3 + 1);
            const float v2 = __ldg(mp + m * 3 + 2);
            float e0 = fmaf(dR[0], v0, fmaf(dR[1], v1, fmaf(dR[2], v2, dt0)));
            float e1 = fmaf(dR[3], v0, fmaf(dR[4], v1, fmaf(dR[5], v2, dt1)));
            float e2 = fmaf(dR[6], v0, fmaf(dR[7], v1, fmaf(dR[8], v2, dt2)));
            float g0 = fmaf(Rg[0], v0, fmaf(Rg[1], v1, fmaf(Rg[2], v2, tg[0])));
            float g1 = fmaf(Rg[3], v0, fmaf(Rg[4], v1, fmaf(Rg[5], v2, tg[1])));
            float g2 = fmaf(Rg[6], v0, fmaf(Rg[7], v1, fmaf(Rg[8], v2, tg[2])));
            adsum += fsqrt(fmaf(e0, e0, fmaf(e1, e1, e2 * e2)));
            // p = g + e; p0/p2 - g0/g2 = (e0*g2 - g0*e2)/(p2*g2)
            float t0 = fmaf(e0, g2, -(g0 * e2));
            float t1 = fmaf(e1, g2, -(g1 * e2));
            float p2 = g2 + e2;
            float r  = frcp(p2 * g2);
            float du = fx * (t0 * r);
            float dv = fy * (t1 * r);
            pjsum += fsqrt(fmaf(du, du, dv * dv));
        }
        s1[tid] = adsum; s2[tid] = pjsum;
        __syncthreads();
        for (int s = 128; s > 0; s >>= 1) {
            if (tid < s) { s1[tid] += s1[tid + s]; s2[tid] += s2[tid + s]; }
            __syncthreads();
        }
        if (tid == 0) {
            const float invM = 1.0f / (float)MPTS;
            out[2 * NS + n] = (s1[0] * invM) / __ldg(diam + obj);
            out[3 * NS + n] = s2[0] * invM;
            float tr = 0.f;
#pragma unroll
            for (int i = 0; i < 9; i++) tr = fmaf(Rp[i], Rg[i], tr);
            tr = fminf(fmaxf(tr, -1.0f), 3.0f);
            out[n] = acosf((tr - 1.0f) * 0.5f) * 57.29577951308232f;
            out[NS + n] = sqrtf(fmaf(dt0, dt0, fmaf(dt1, dt1, dt2 * dt2))) * 100.0f;
        }
    }
}

extern "C" void kernel_launch(void* const* d_in, const int* in_sizes, int n_in,
                              void* d_out, int out_size) {
    (void)in_sizes; (void)n_in; (void)out_size;
    const int*   obj_id = (const int*)  d_in[0];
    const float* camK   = (const float*)d_in[1];
    const float* gtR    = (const float*)d_in[2];
    const float* gtT    = (const float*)d_in[3];
    const float* prR    = (const float*)d_in[4];
    const float* prT    = (const float*)d_in[5];
    const float* coord  = (const float*)d_in[6];
    const void*  mask   =               d_in[7];
    const float* mesh   = (const float*)d_in[8];
    const float* diam   = (const float*)d_in[9];
    float* out = (float*)d_out;

    score_kernel<<<2 * NS, BLOCK>>>(obj_id, camK, gtR, gtT, prR, prT,
                                    coord, mask, mesh, diam, out);
}